// round 4
// baseline (speedup 1.0000x reference)
#include <cuda_runtime.h>
#include <cuda_bf16.h>
#include <cstdint>
#include <cstdio>

// Problem constants
#define BDIM 16384
#define OBSD 512
#define HD   1024
#define NAG  9

// ---------------------------------------------------------------------------
// Static scratch (no allocation allowed)
// ---------------------------------------------------------------------------
__device__ __align__(16) __nv_bfloat16 g_obs [BDIM * OBSD];       // bf16 obs
__device__ __align__(16) __nv_bfloat16 g_W1t [HD * OBSD];         // [N=H][K=OBS]
__device__ __align__(16) __nv_bfloat16 g_W2t [HD * HD];           // [H][H]
__device__ __align__(16) __nv_bfloat16 g_Wc1t[(HD/2) * HD];       // [512][1024]
__device__ __align__(16) __nv_bfloat16 g_Wt1t[(HD/2) * HD];       // [512][1024]
__device__ __align__(16) __nv_bfloat16 g_Wkt [HD * HD];           // summed+transposed Wk1
__device__ __align__(16) __nv_bfloat16 g_g1  [BDIM * HD];
__device__ __align__(16) __nv_bfloat16 g_g2  [BDIM * HD];
__device__ __align__(16) __nv_bfloat16 g_hc  [BDIM * (HD/2)];
__device__ __align__(16) __nv_bfloat16 g_ht  [BDIM * (HD/2)];
__device__ __align__(16) __nv_bfloat16 g_hk  [BDIM * HD];

// ---------------------------------------------------------------------------
// Helpers
// ---------------------------------------------------------------------------
__device__ __forceinline__ void cp_async16(void* smem, const void* gmem) {
    uint32_t s = (uint32_t)__cvta_generic_to_shared(smem);
    asm volatile("cp.async.cg.shared.global [%0], [%1], 16;\n" :: "r"(s), "l"(gmem));
}
__device__ __forceinline__ void cp_async_commit() {
    asm volatile("cp.async.commit_group;\n");
}
__device__ __forceinline__ void cp_async_wait_all() {
    asm volatile("cp.async.wait_group 0;\n");
}

__device__ __forceinline__ void mma_bf16(float* c, const uint32_t* a,
                                         uint32_t b0, uint32_t b1) {
    asm volatile(
        "mma.sync.aligned.m16n8k16.row.col.f32.bf16.bf16.f32 "
        "{%0,%1,%2,%3}, {%4,%5,%6,%7}, {%8,%9}, {%0,%1,%2,%3};\n"
        : "+f"(c[0]), "+f"(c[1]), "+f"(c[2]), "+f"(c[3])
        : "r"(a[0]), "r"(a[1]), "r"(a[2]), "r"(a[3]), "r"(b0), "r"(b1));
}

// ---------------------------------------------------------------------------
// Prep kernels
// ---------------------------------------------------------------------------
__global__ void k_cvt_bf16(const float* __restrict__ src,
                           __nv_bfloat16* __restrict__ dst, int n) {
    int i = blockIdx.x * blockDim.x + threadIdx.x;
    int stride = gridDim.x * blockDim.x;
    for (; i < n; i += stride) dst[i] = __float2bfloat16(src[i]);
}

// dst[n*K + k] = bf16(src[k*N + n] (+ src2[k*N + n]))   src: [K,N] fp32
__global__ void k_transpose_cvt(const float* __restrict__ src,
                                const float* __restrict__ src2,
                                __nv_bfloat16* __restrict__ dst,
                                int K, int N) {
    __shared__ float tile[32][33];
    int k0 = blockIdx.y * 32, n0 = blockIdx.x * 32;
    int tx = threadIdx.x, ty = threadIdx.y;  // 32 x 8
    #pragma unroll
    for (int i = ty; i < 32; i += 8) {
        float v = src[(size_t)(k0 + i) * N + n0 + tx];
        if (src2) v += src2[(size_t)(k0 + i) * N + n0 + tx];
        tile[i][tx] = v;
    }
    __syncthreads();
    #pragma unroll
    for (int i = ty; i < 32; i += 8)
        dst[(size_t)(n0 + i) * K + k0 + tx] = __float2bfloat16(tile[tx][i]);
}

// ---------------------------------------------------------------------------
// Main GEMM:  C[M,N] = relu(A[M,K] @ Bt[N,K]^T + bias[N])  (bf16 in/out, fp32 acc)
// Block tile 128x128x32, 8 warps (4m x 2n), warp tile 32x64, mma m16n8k16.
// ---------------------------------------------------------------------------
#define BM 128
#define BN 128
#define BK 32
#define BKP 40   // padded row stride in bf16 (80B, 16B aligned, conflict-free frags)

__global__ __launch_bounds__(256, 2)
void k_gemm_bf16_relu(const __nv_bfloat16* __restrict__ A,
                      const __nv_bfloat16* __restrict__ Bt,
                      const float* __restrict__ bias,
                      __nv_bfloat16* __restrict__ C,
                      int M, int N, int K) {
    __shared__ __nv_bfloat16 As[2][BM * BKP];
    __shared__ __nv_bfloat16 Bs[2][BN * BKP];

    const int tid  = threadIdx.x;
    const int wid  = tid >> 5;
    const int lane = tid & 31;
    const int g    = lane >> 2;   // group id (0..7)
    const int tg   = lane & 3;    // thread in group (0..3)
    const int warp_m = (wid & 3) * 32;
    const int warp_n = (wid >> 2) * 64;
    const int m0 = blockIdx.y * BM;
    const int n0 = blockIdx.x * BN;

    float acc[2][8][4];
    #pragma unroll
    for (int a = 0; a < 2; a++)
        #pragma unroll
        for (int b = 0; b < 8; b++)
            #pragma unroll
            for (int c = 0; c < 4; c++) acc[a][b][c] = 0.f;

    const int KT = K / BK;

    // tile loader: 128 rows x 32 cols bf16 = 512 x 16B chunks for each of A,B
    auto load_tile = [&](int kt, int buf) {
        const int k0 = kt * BK;
        #pragma unroll
        for (int i = 0; i < 2; i++) {
            int c   = tid + i * 256;
            int row = c >> 2;
            int cc  = (c & 3) * 8;
            cp_async16(&As[buf][row * BKP + cc],
                       A + (size_t)(m0 + row) * K + k0 + cc);
            cp_async16(&Bs[buf][row * BKP + cc],
                       Bt + (size_t)(n0 + row) * K + k0 + cc);
        }
        cp_async_commit();
    };

    load_tile(0, 0);

    for (int kt = 0; kt < KT; kt++) {
        const int buf = kt & 1;
        cp_async_wait_all();
        __syncthreads();
        if (kt + 1 < KT) load_tile(kt + 1, buf ^ 1);

        #pragma unroll
        for (int ks = 0; ks < 2; ks++) {
            const int kk = ks * 16;
            uint32_t afr[2][4];
            #pragma unroll
            for (int mi = 0; mi < 2; mi++) {
                const int r = warp_m + mi * 16 + g;
                const __nv_bfloat16* base = &As[buf][0];
                afr[mi][0] = *(const uint32_t*)(base + (r)     * BKP + kk +     2 * tg);
                afr[mi][1] = *(const uint32_t*)(base + (r + 8) * BKP + kk +     2 * tg);
                afr[mi][2] = *(const uint32_t*)(base + (r)     * BKP + kk + 8 + 2 * tg);
                afr[mi][3] = *(const uint32_t*)(base + (r + 8) * BKP + kk + 8 + 2 * tg);
            }
            #pragma unroll
            for (int ni = 0; ni < 8; ni++) {
                const int n = warp_n + ni * 8 + g;
                const __nv_bfloat16* bbase = &Bs[buf][0];
                uint32_t b0 = *(const uint32_t*)(bbase + n * BKP + kk +     2 * tg);
                uint32_t b1 = *(const uint32_t*)(bbase + n * BKP + kk + 8 + 2 * tg);
                #pragma unroll
                for (int mi = 0; mi < 2; mi++)
                    mma_bf16(acc[mi][ni], afr[mi], b0, b1);
            }
        }
        __syncthreads();
    }

    // Epilogue: bias + relu + bf16 store
    #pragma unroll
    for (int mi = 0; mi < 2; mi++) {
        const int r = m0 + warp_m + mi * 16 + g;
        #pragma unroll
        for (int ni = 0; ni < 8; ni++) {
            const int col = n0 + warp_n + ni * 8 + 2 * tg;
            float bi0 = bias[col], bi1 = bias[col + 1];
            float v0 = fmaxf(acc[mi][ni][0] + bi0, 0.f);
            float v1 = fmaxf(acc[mi][ni][1] + bi1, 0.f);
            float v2 = fmaxf(acc[mi][ni][2] + bi0, 0.f);
            float v3 = fmaxf(acc[mi][ni][3] + bi1, 0.f);
            __nv_bfloat162 p0 = __floats2bfloat162_rn(v0, v1);
            __nv_bfloat162 p1 = __floats2bfloat162_rn(v2, v3);
            *(__nv_bfloat162*)&C[(size_t)r * N + col]       = p0;
            *(__nv_bfloat162*)&C[(size_t)(r + 8) * N + col] = p1;
        }
    }
}

// ---------------------------------------------------------------------------
// Finalize: per-row dot products + sigmoid + broadcast to N=9, 3 outputs.
// One warp per row.
// ---------------------------------------------------------------------------
__global__ void k_finalize(const __nv_bfloat16* __restrict__ hc,
                           const __nv_bfloat16* __restrict__ ht,
                           const __nv_bfloat16* __restrict__ hk,
                           const float* __restrict__ Wc2, const float* __restrict__ bc2,
                           const float* __restrict__ Wt2, const float* __restrict__ bt2,
                           const float* __restrict__ Wk2, const float* __restrict__ bk2,
                           float* __restrict__ out) {
    const int lane = threadIdx.x & 31;
    const int row  = blockIdx.x * (blockDim.x >> 5) + (threadIdx.x >> 5);
    if (row >= BDIM) return;

    const __nv_bfloat16* pc = hc + (size_t)row * (HD / 2);
    const __nv_bfloat16* pt = ht + (size_t)row * (HD / 2);
    const __nv_bfloat16* pk = hk + (size_t)row * HD;

    float sc = 0.f, st = 0.f, sk = 0.f;
    #pragma unroll 4
    for (int j = lane; j < HD / 2; j += 32) {
        sc += __bfloat162float(pc[j]) * Wc2[j];
        st += __bfloat162float(pt[j]) * Wt2[j];
    }
    #pragma unroll 4
    for (int j = lane; j < HD; j += 32)
        sk += __bfloat162float(pk[j]) * Wk2[j];

    #pragma unroll
    for (int o = 16; o > 0; o >>= 1) {
        sc += __shfl_xor_sync(0xFFFFFFFFu, sc, o);
        st += __shfl_xor_sync(0xFFFFFFFFu, st, o);
        sk += __shfl_xor_sync(0xFFFFFFFFu, sk, o);
    }

    if (lane == 0) {
        float cov = 1.f / (1.f + expf(-(sc + bc2[0])));
        float trk = 1.f / (1.f + expf(-(st + bt2[0])));
        float cop = 1.f / (1.f + expf(-(sk + bk2[0])));
        float* o0 = out + (size_t)row * NAG;
        float* o1 = out + (size_t)BDIM * NAG + (size_t)row * NAG;
        float* o2 = out + (size_t)2 * BDIM * NAG + (size_t)row * NAG;
        #pragma unroll
        for (int j = 0; j < NAG; j++) { o0[j] = cov; o1[j] = trk; o2[j] = cop; }
    }
}

// ---------------------------------------------------------------------------
// Launch
// ---------------------------------------------------------------------------
extern "C" void kernel_launch(void* const* d_in, const int* in_sizes, int n_in,
                              void* d_out, int out_size) {
    (void)in_sizes; (void)n_in; (void)out_size;

    const float* obs = (const float*)d_in[0];
    // d_in[1] = agent_positions (unused by the math)
    const float* W1  = (const float*)d_in[2];
    const float* b1  = (const float*)d_in[3];
    const float* W2  = (const float*)d_in[4];
    const float* b2  = (const float*)d_in[5];
    const float* Wc1 = (const float*)d_in[6];
    const float* bc1 = (const float*)d_in[7];
    const float* Wc2 = (const float*)d_in[8];
    const float* bc2 = (const float*)d_in[9];
    const float* Wt1 = (const float*)d_in[10];
    const float* bt1 = (const float*)d_in[11];
    const float* Wt2 = (const float*)d_in[12];
    const float* bt2 = (const float*)d_in[13];
    const float* Wk1 = (const float*)d_in[14];
    const float* bk1 = (const float*)d_in[15];
    const float* Wk2 = (const float*)d_in[16];
    const float* bk2 = (const float*)d_in[17];
    float* out = (float*)d_out;

    // symbol addresses for scratch
    void *p_obs, *p_W1t, *p_W2t, *p_Wc1t, *p_Wt1t, *p_Wkt,
         *p_g1, *p_g2, *p_hc, *p_ht, *p_hk;
    cudaGetSymbolAddress(&p_obs,  g_obs);
    cudaGetSymbolAddress(&p_W1t,  g_W1t);
    cudaGetSymbolAddress(&p_W2t,  g_W2t);
    cudaGetSymbolAddress(&p_Wc1t, g_Wc1t);
    cudaGetSymbolAddress(&p_Wt1t, g_Wt1t);
    cudaGetSymbolAddress(&p_Wkt,  g_Wkt);
    cudaGetSymbolAddress(&p_g1,   g_g1);
    cudaGetSymbolAddress(&p_g2,   g_g2);
    cudaGetSymbolAddress(&p_hc,   g_hc);
    cudaGetSymbolAddress(&p_ht,   g_ht);
    cudaGetSymbolAddress(&p_hk,   g_hk);

    // 1) obs -> bf16
    k_cvt_bf16<<<1024, 256>>>(obs, (__nv_bfloat16*)p_obs, BDIM * OBSD);

    // 2) weight prep (transpose to [N][K], bf16; Wk folded: Wk1[:H]+Wk1[H:])
    dim3 tb(32, 8);
    k_transpose_cvt<<<dim3(HD / 32, OBSD / 32), tb>>>(W1, nullptr, (__nv_bfloat16*)p_W1t, OBSD, HD);
    k_transpose_cvt<<<dim3(HD / 32, HD / 32),   tb>>>(W2, nullptr, (__nv_bfloat16*)p_W2t, HD, HD);
    k_transpose_cvt<<<dim3((HD/2) / 32, HD / 32), tb>>>(Wc1, nullptr, (__nv_bfloat16*)p_Wc1t, HD, HD / 2);
    k_transpose_cvt<<<dim3((HD/2) / 32, HD / 32), tb>>>(Wt1, nullptr, (__nv_bfloat16*)p_Wt1t, HD, HD / 2);
    k_transpose_cvt<<<dim3(HD / 32, HD / 32),   tb>>>(Wk1, Wk1 + (size_t)HD * HD, (__nv_bfloat16*)p_Wkt, HD, HD);

    // 3) backbone
    k_gemm_bf16_relu<<<dim3(HD / BN, BDIM / BM), 256>>>(
        (const __nv_bfloat16*)p_obs, (const __nv_bfloat16*)p_W1t, b1,
        (__nv_bfloat16*)p_g1, BDIM, HD, OBSD);
    k_gemm_bf16_relu<<<dim3(HD / BN, BDIM / BM), 256>>>(
        (const __nv_bfloat16*)p_g1, (const __nv_bfloat16*)p_W2t, b2,
        (__nv_bfloat16*)p_g2, BDIM, HD, HD);

    // 4) heads
    k_gemm_bf16_relu<<<dim3((HD/2) / BN, BDIM / BM), 256>>>(
        (const __nv_bfloat16*)p_g2, (const __nv_bfloat16*)p_Wc1t, bc1,
        (__nv_bfloat16*)p_hc, BDIM, HD / 2, HD);
    k_gemm_bf16_relu<<<dim3((HD/2) / BN, BDIM / BM), 256>>>(
        (const __nv_bfloat16*)p_g2, (const __nv_bfloat16*)p_Wt1t, bt1,
        (__nv_bfloat16*)p_ht, BDIM, HD / 2, HD);
    k_gemm_bf16_relu<<<dim3(HD / BN, BDIM / BM), 256>>>(
        (const __nv_bfloat16*)p_g2, (const __nv_bfloat16*)p_Wkt, bk1,
        (__nv_bfloat16*)p_hk, BDIM, HD, HD);

    // 5) final dots + sigmoid + broadcast
    k_finalize<<<BDIM / 8, 256>>>(
        (const __nv_bfloat16*)p_hc, (const __nv_bfloat16*)p_ht, (const __nv_bfloat16*)p_hk,
        Wc2, bc2, Wt2, bt2, Wk2, bk2, out);
}

// round 8
// speedup vs baseline: 2.4341x; 2.4341x over previous
#include <cuda_runtime.h>
#include <cuda_bf16.h>
#include <cstdint>

// Problem constants
#define BDIM 16384
#define OBSD 512
#define HD   1024
#define NAG  9
#define NTOTH 2048          // fused head GEMM N (coop 1024 | cov 512 | trk 512)
#define NTILES (NTOTH/128)  // 16 column tiles in head GEMM

// tcgen05-path smem layout (dynamic)
#define TC_STAGE_B 16384                    // 128 rows x 128B (K=64 bf16, SW128)
#define TC_SM_A    1024
#define TC_SM_B    (TC_SM_A + 4 * TC_STAGE_B)
#define TC_SMEM    (TC_SM_B + 4 * TC_STAGE_B)   // 132096 B

#if defined(__CUDA_ARCH_FEAT_SM103_ALL)
#define GEMM_BOUNDS __launch_bounds__(256, 1)
#else
#define GEMM_BOUNDS __launch_bounds__(256, 2)
#endif

// ---------------------------------------------------------------------------
// Static scratch (no allocation allowed)
// ---------------------------------------------------------------------------
__device__ __align__(16) __nv_bfloat16 g_obs [BDIM * OBSD];
__device__ __align__(16) __nv_bfloat16 g_W1t [HD * OBSD];      // [1024][512]
__device__ __align__(16) __nv_bfloat16 g_W2t [HD * HD];        // [1024][1024]
__device__ __align__(16) __nv_bfloat16 g_Wall[NTOTH * HD];     // [coop|cov|trk][1024]
__device__ __align__(16) float         g_ball[NTOTH];          // combined bias
__device__ __align__(16) float         g_w2v [NTOTH];          // combined layer-2 weights
__device__ __align__(16) __nv_bfloat16 g_g1  [BDIM * HD];
__device__ __align__(16) __nv_bfloat16 g_g2  [BDIM * HD];
__device__ __align__(16) float         g_part[NTILES * BDIM];  // per-tile partial logits

// ---------------------------------------------------------------------------
// Common PTX helpers
// ---------------------------------------------------------------------------
__device__ __forceinline__ void cpa16p(void* smem, const void* gmem) {
    uint32_t s = (uint32_t)__cvta_generic_to_shared(smem);
    asm volatile("cp.async.cg.shared.global [%0], [%1], 16;\n" :: "r"(s), "l"(gmem));
}
__device__ __forceinline__ void cpa16a(uint32_t s, const void* gmem) {
    asm volatile("cp.async.cg.shared.global [%0], [%1], 16;\n" :: "r"(s), "l"(gmem));
}
__device__ __forceinline__ void cpa_commit() {
    asm volatile("cp.async.commit_group;\n" ::: "memory");
}
__device__ __forceinline__ void cpa_wait0() {
    asm volatile("cp.async.wait_group 0;\n" ::: "memory");
}
__device__ __forceinline__ void cpa_wait2() {
    asm volatile("cp.async.wait_group 2;\n" ::: "memory");
}

// legacy HMMA
__device__ __forceinline__ void mma_bf16(float* c, const uint32_t* a,
                                         uint32_t b0, uint32_t b1) {
    asm volatile(
        "mma.sync.aligned.m16n8k16.row.col.f32.bf16.bf16.f32 "
        "{%0,%1,%2,%3}, {%4,%5,%6,%7}, {%8,%9}, {%0,%1,%2,%3};\n"
        : "+f"(c[0]), "+f"(c[1]), "+f"(c[2]), "+f"(c[3])
        : "r"(a[0]), "r"(a[1]), "r"(a[2]), "r"(a[3]), "r"(b0), "r"(b1));
}

#if defined(__CUDA_ARCH_FEAT_SM103_ALL)
// ---------------- tcgen05-only helpers (compiled only in the 'a' pass) -----
__device__ __forceinline__ void mbar_init(uint32_t m, uint32_t cnt) {
    asm volatile("mbarrier.init.shared.b64 [%0], %1;" :: "r"(m), "r"(cnt) : "memory");
}
__device__ __forceinline__ void mbar_inval(uint32_t m) {
    asm volatile("mbarrier.inval.shared.b64 [%0];" :: "r"(m) : "memory");
}
__device__ __forceinline__ void mbar_wait(uint32_t m, uint32_t parity) {
    asm volatile(
        "{\n\t.reg .pred P;\n"
        "W%=:\n\t"
        "mbarrier.try_wait.parity.acquire.cta.shared::cta.b64 P, [%0], %1, 0x989680;\n\t"
        "@P bra.uni D%=;\n\t"
        "bra.uni W%=;\n"
        "D%=:\n\t}"
        :: "r"(m), "r"(parity) : "memory");
}
__device__ __forceinline__ void mma_f16_ss(uint32_t d_tmem, uint64_t a_desc,
                                           uint64_t b_desc, uint32_t idesc,
                                           bool accum) {
    uint32_t en = accum ? 1u : 0u;
    uint32_t z = 0u;
    asm volatile(
        "{\n\t.reg .pred p;\n\t"
        "setp.ne.u32 p, %5, 0;\n\t"
        "tcgen05.mma.cta_group::1.kind::f16 [%0], %1, %2, %3, {%4, %4, %4, %4}, p;\n\t"
        "}"
        :: "r"(d_tmem), "l"(a_desc), "l"(b_desc), "r"(idesc), "r"(z), "r"(en)
        : "memory");
}
__device__ __forceinline__ void tmem_ld32(uint32_t* r, uint32_t addr) {
    asm volatile(
        "tcgen05.ld.sync.aligned.32x32b.x32.b32 "
        "{%0, %1, %2, %3, %4, %5, %6, %7, "
        " %8, %9, %10, %11, %12, %13, %14, %15, "
        " %16, %17, %18, %19, %20, %21, %22, %23, "
        " %24, %25, %26, %27, %28, %29, %30, %31}, [%32];"
        : "=r"(r[0]),  "=r"(r[1]),  "=r"(r[2]),  "=r"(r[3]),
          "=r"(r[4]),  "=r"(r[5]),  "=r"(r[6]),  "=r"(r[7]),
          "=r"(r[8]),  "=r"(r[9]),  "=r"(r[10]), "=r"(r[11]),
          "=r"(r[12]), "=r"(r[13]), "=r"(r[14]), "=r"(r[15]),
          "=r"(r[16]), "=r"(r[17]), "=r"(r[18]), "=r"(r[19]),
          "=r"(r[20]), "=r"(r[21]), "=r"(r[22]), "=r"(r[23]),
          "=r"(r[24]), "=r"(r[25]), "=r"(r[26]), "=r"(r[27]),
          "=r"(r[28]), "=r"(r[29]), "=r"(r[30]), "=r"(r[31])
        : "r"(addr));
}
// SW128 K-major descriptor base (layout=SW128, version=1, SBO=64, LBO=1)
__device__ __forceinline__ uint64_t make_desc(uint32_t smem_addr) {
    const uint64_t base =
        (uint64_t(2) << 61) | (uint64_t(1) << 46) | (uint64_t(64) << 32) | (uint64_t(1) << 16);
    return base | ((uint64_t)(smem_addr >> 4) & 0x3FFF);
}
#endif  // __CUDA_ARCH_FEAT_SM103_ALL

// ---------------------------------------------------------------------------
// Prep kernels
// ---------------------------------------------------------------------------
__global__ void k_cvt_bf16_v4(const float4* __restrict__ src,
                              __nv_bfloat16* __restrict__ dst, int n4) {
    int i = blockIdx.x * blockDim.x + threadIdx.x;
    int stride = gridDim.x * blockDim.x;
    for (; i < n4; i += stride) {
        float4 v = src[i];
        __nv_bfloat162 p0 = __floats2bfloat162_rn(v.x, v.y);
        __nv_bfloat162 p1 = __floats2bfloat162_rn(v.z, v.w);
        uint2 o;
        o.x = *(uint32_t*)&p0;
        o.y = *(uint32_t*)&p1;
        *(uint2*)&dst[(size_t)i * 4] = o;
    }
}

// All 5 weight transposes in one launch (blockIdx.z selects).
// dst[n*K + k] = bf16(src[k*N + n] (+ src2[k*N + n]))
__global__ void k_prep_weights(const float* __restrict__ W1,
                               const float* __restrict__ W2,
                               const float* __restrict__ Wc1,
                               const float* __restrict__ Wt1,
                               const float* __restrict__ Wk1) {
    const float* src = nullptr; const float* src2 = nullptr;
    __nv_bfloat16* dst = nullptr; int K = 0, N = 0;
    switch (blockIdx.z) {
        case 0: src = W1;  dst = g_W1t;                K = OBSD; N = HD;    break;
        case 1: src = W2;  dst = g_W2t;                K = HD;   N = HD;    break;
        case 2: src = Wc1; dst = g_Wall + 1024 * HD;   K = HD;   N = HD/2;  break;
        case 3: src = Wt1; dst = g_Wall + 1536 * HD;   K = HD;   N = HD/2;  break;
        case 4: src = Wk1; src2 = Wk1 + (size_t)HD*HD; dst = g_Wall; K = HD; N = HD; break;
    }
    int n0 = blockIdx.x * 32, k0 = blockIdx.y * 32;
    if (n0 >= N || k0 >= K) return;

    __shared__ float tile[32][33];
    int tx = threadIdx.x, ty = threadIdx.y;  // 32 x 8
    #pragma unroll
    for (int i = ty; i < 32; i += 8) {
        float v = src[(size_t)(k0 + i) * N + n0 + tx];
        if (src2) v += src2[(size_t)(k0 + i) * N + n0 + tx];
        tile[i][tx] = v;
    }
    __syncthreads();
    #pragma unroll
    for (int i = ty; i < 32; i += 8)
        dst[(size_t)(n0 + i) * K + k0 + tx] = __float2bfloat16(tile[tx][i]);
}

// Combined bias / layer-2 weight vectors + zero partial buffer.
__global__ void k_head_vecs_zero(const float* __restrict__ bk1, const float* __restrict__ Wk2,
                                 const float* __restrict__ bc1, const float* __restrict__ Wc2,
                                 const float* __restrict__ bt1, const float* __restrict__ Wt2) {
    int i = blockIdx.x * blockDim.x + threadIdx.x;
    if (i < NTOTH) {
        float b, w;
        if (i < 1024)      { b = bk1[i];        w = Wk2[i]; }
        else if (i < 1536) { b = bc1[i - 1024]; w = Wc2[i - 1024]; }
        else               { b = bt1[i - 1536]; w = Wt2[i - 1536]; }
        g_ball[i] = b; g_w2v[i] = w;
    }
    if (i < NTILES * BDIM) g_part[i] = 0.f;
}

// ---------------------------------------------------------------------------
// Unified GEMM: C[M,N] = relu(A[M,K] @ Bt[N,K]^T + bias)        (FUSED=false)
//            or part[tile][r] += relu(...)[r,:] . w2[:]          (FUSED=true)
// 256 threads, 128x128 CTA tile. Two bodies selected at device-compile time:
//   sm_103a pass  -> tcgen05 SS pipeline (dynamic smem, TC_SMEM bytes)
//   sm_103 pass   -> mma.sync m16n8k16 (static smem, BK=64 double buffer)
// ---------------------------------------------------------------------------
template<bool FUSED>
__global__ void GEMM_BOUNDS
k_gemm(const __nv_bfloat16* __restrict__ A,
       const __nv_bfloat16* __restrict__ Bt,
       const float* __restrict__ bias,
       const float* __restrict__ w2,
       __nv_bfloat16* __restrict__ C,
       float* __restrict__ part,
       int K, int Ntot) {
    const int tid = threadIdx.x, wid = tid >> 5, lane = tid & 31;
    const int n0 = blockIdx.x * 128, m0 = blockIdx.y * 128;

#if defined(__CUDA_ARCH_FEAT_SM103_ALL)
    // =================== tcgen05 path ===================
    extern __shared__ __align__(1024) char smem[];
    const uint32_t sb = (uint32_t)__cvta_generic_to_shared(smem);

    if (wid == 0) {
        asm volatile("tcgen05.alloc.cta_group::1.sync.aligned.shared::cta.b32 [%0], %1;"
                     :: "r"(sb + 0), "r"(128) : "memory");
        asm volatile("tcgen05.relinquish_alloc_permit.cta_group::1.sync.aligned;");
    }
    if (tid == 0) mbar_init(sb + 16, 1);
    __syncthreads();
    uint32_t tmem;
    asm volatile("ld.shared.b32 %0, [%1];" : "=r"(tmem) : "r"(sb + 0));

    const __nv_bfloat16* gA = A + (size_t)m0 * K;
    const __nv_bfloat16* gB = Bt + (size_t)n0 * K;

    auto load_stage = [&](int s) {
        const uint32_t ab = sb + TC_SM_A + (s & 3) * TC_STAGE_B;
        const uint32_t bb = sb + TC_SM_B + (s & 3) * TC_STAGE_B;
        const int k0 = s * 64;
        #pragma unroll
        for (int i = 0; i < 4; i++) {      // 128 rows x 8 chunks = 1024 / 256 thr
            int c = tid + i * 256;
            int row = c >> 3, col = c & 7;
            uint32_t off = row * 128 + col * 16;
            off ^= (off >> 3) & 0x70;      // SW128 swizzle
            cpa16a(ab + off, gA + (size_t)row * K + k0 + col * 8);
            cpa16a(bb + off, gB + (size_t)row * K + k0 + col * 8);
        }
    };

    const int T = K / 64;
    #pragma unroll
    for (int s = 0; s < 3; s++) { load_stage(s); cpa_commit(); }

    // idesc: f32 acc | bf16 A | bf16 B | N=128 | M=128
    const uint32_t IDESC = (1u << 4) | (1u << 7) | (1u << 10) | (16u << 17) | (8u << 24);
    const uint64_t ad0 = make_desc(sb + TC_SM_A);
    const uint64_t bd0 = make_desc(sb + TC_SM_B);

    for (int t = 0; t < T; t++) {
        cpa_wait2();
        __syncthreads();
        asm volatile("fence.proxy.async.shared::cta;" ::: "memory");
        if (t > 0) mbar_wait(sb + 16, (t - 1) & 1);
        if (tid == 0) {
            uint64_t ad = ad0 + (uint64_t)(t & 3) * (TC_STAGE_B >> 4);
            uint64_t bd = bd0 + (uint64_t)(t & 3) * (TC_STAGE_B >> 4);
            #pragma unroll
            for (int kk = 0; kk < 4; kk++)   // 4 x K=16 dispatches (32B apart)
                mma_f16_ss(tmem, ad + kk * 2, bd + kk * 2, IDESC, (t > 0) || (kk > 0));
            asm volatile(
                "tcgen05.commit.cta_group::1.mbarrier::arrive::one.shared::cluster.b64 [%0];"
                :: "r"(sb + 16) : "memory");
        }
        if (t + 3 < T) load_stage(t + 3);
        cpa_commit();
    }
    mbar_wait(sb + 16, (T - 1) & 1);
    asm volatile("tcgen05.fence::after_thread_sync;" ::: "memory");

    // Epilogue: warps 0-3 cols [0,64), warps 4-7 cols [64,128); rows = (wid&3)*32+lane
    const int r  = m0 + (wid & 3) * 32 + lane;
    const int cb = (wid >> 2) * 64;
    if (!FUSED) {
        #pragma unroll
        for (int ch = 0; ch < 2; ch++) {
            uint32_t d[32];
            tmem_ld32(d, tmem + cb + ch * 32);
            asm volatile("tcgen05.wait::ld.sync.aligned;" ::: "memory");
            const int col0 = n0 + cb + ch * 32;
            #pragma unroll
            for (int q = 0; q < 4; q++) {
                uint4 v;
                #pragma unroll
                for (int e = 0; e < 4; e++) {
                    int c = q * 8 + e * 2;
                    float x0 = fmaxf(__uint_as_float(d[c])     + bias[col0 + c],     0.f);
                    float x1 = fmaxf(__uint_as_float(d[c + 1]) + bias[col0 + c + 1], 0.f);
                    __nv_bfloat162 p = __floats2bfloat162_rn(x0, x1);
                    ((uint32_t*)&v)[e] = *(uint32_t*)&p;
                }
                *(uint4*)&C[(size_t)r * Ntot + col0 + q * 8] = v;
            }
        }
    } else {
        float ps = 0.f;
        #pragma unroll
        for (int ch = 0; ch < 2; ch++) {
            uint32_t d[32];
            tmem_ld32(d, tmem + cb + ch * 32);
            asm volatile("tcgen05.wait::ld.sync.aligned;" ::: "memory");
            const int col0 = n0 + cb + ch * 32;
            #pragma unroll
            for (int c = 0; c < 32; c++) {
                float x = fmaxf(__uint_as_float(d[c]) + bias[col0 + c], 0.f);
                ps += x * w2[col0 + c];
            }
        }
        // exactly 2 contributions per (tile,row): wid and wid+4 -> commutative -> deterministic
        atomicAdd(&part[(size_t)blockIdx.x * BDIM + r], ps);
    }

    asm volatile("tcgen05.fence::before_thread_sync;" ::: "memory");
    __syncthreads();
    if (tid == 0) mbar_inval(sb + 16);
    __syncthreads();
    if (wid == 0)
        asm volatile("tcgen05.dealloc.cta_group::1.sync.aligned.b32 %0, %1;"
                     :: "r"(tmem), "r"(128));

#else
    // =================== mma.sync fallback (BK=64, double buffer) ===========
    #define BKP 72   // 64 + 8 pad elements (144 B row) -> conflict-free frags
    __shared__ __nv_bfloat16 As[2][128 * BKP];
    __shared__ __nv_bfloat16 Bs[2][128 * BKP];

    const int g  = lane >> 2;
    const int tg = lane & 3;
    const int warp_m = (wid & 3) * 32;
    const int warp_n = (wid >> 2) * 64;

    float acc[2][8][4];
    #pragma unroll
    for (int a = 0; a < 2; a++)
        #pragma unroll
        for (int b = 0; b < 8; b++)
            #pragma unroll
            for (int c = 0; c < 4; c++) acc[a][b][c] = 0.f;

    const int KT = K / 64;

    auto load_tile = [&](int kt, int buf) {
        const int k0 = kt * 64;
        #pragma unroll
        for (int i = 0; i < 4; i++) {    // 128 rows x 8 x 16B chunks per matrix
            int c   = tid + i * 256;
            int row = c >> 3;
            int cc  = (c & 7) * 8;
            cpa16p(&As[buf][row * BKP + cc], A + (size_t)(m0 + row) * K + k0 + cc);
            cpa16p(&Bs[buf][row * BKP + cc], Bt + (size_t)(n0 + row) * K + k0 + cc);
        }
        cpa_commit();
    };

    load_tile(0, 0);

    for (int kt = 0; kt < KT; kt++) {
        const int buf = kt & 1;
        cpa_wait0();
        __syncthreads();
        if (kt + 1 < KT) load_tile(kt + 1, buf ^ 1);

        #pragma unroll
        for (int ks = 0; ks < 4; ks++) {
            const int kk = ks * 16;
            uint32_t afr[2][4];
            #pragma unroll
            for (int mi = 0; mi < 2; mi++) {
                const int rr = warp_m + mi * 16 + g;
                const __nv_bfloat16* base = &As[buf][0];
                afr[mi][0] = *(const uint32_t*)(base + (rr)     * BKP + kk +     2 * tg);
                afr[mi][1] = *(const uint32_t*)(base + (rr + 8) * BKP + kk +     2 * tg);
                afr[mi][2] = *(const uint32_t*)(base + (rr)     * BKP + kk + 8 + 2 * tg);
                afr[mi][3] = *(const uint32_t*)(base + (rr + 8) * BKP + kk + 8 + 2 * tg);
            }
            #pragma unroll
            for (int ni = 0; ni < 8; ni++) {
                const int nn = warp_n + ni * 8 + g;
                const __nv_bfloat16* bbase = &Bs[buf][0];
                uint32_t b0 = *(const uint32_t*)(bbase + nn * BKP + kk +     2 * tg);
                uint32_t b1 = *(const uint32_t*)(bbase + nn * BKP + kk + 8 + 2 * tg);
                #pragma unroll
                for (int mi = 0; mi < 2; mi++)
                    mma_bf16(acc[mi][ni], afr[mi], b0, b1);
            }
        }
        __syncthreads();
    }

    if (!FUSED) {
        #pragma unroll
        for (int mi = 0; mi < 2; mi++) {
            const int rr = m0 + warp_m + mi * 16 + g;
            #pragma unroll
            for (int ni = 0; ni < 8; ni++) {
                const int col = n0 + warp_n + ni * 8 + 2 * tg;
                float bi0 = bias[col], bi1 = bias[col + 1];
                float v0 = fmaxf(acc[mi][ni][0] + bi0, 0.f);
                float v1 = fmaxf(acc[mi][ni][1] + bi1, 0.f);
                float v2 = fmaxf(acc[mi][ni][2] + bi0, 0.f);
                float v3 = fmaxf(acc[mi][ni][3] + bi1, 0.f);
                __nv_bfloat162 p0 = __floats2bfloat162_rn(v0, v1);
                __nv_bfloat162 p1 = __floats2bfloat162_rn(v2, v3);
                *(__nv_bfloat162*)&C[(size_t)rr * Ntot + col]       = p0;
                *(__nv_bfloat162*)&C[(size_t)(rr + 8) * Ntot + col] = p1;
            }
        }
    } else {
        // Fused epilogue: per-row dot with w2, reduce over tg lanes, 2 atomics/cell.
        #pragma unroll
        for (int mi = 0; mi < 2; mi++) {
            float s0 = 0.f, s1 = 0.f;   // rows rr, rr+8
            #pragma unroll
            for (int ni = 0; ni < 8; ni++) {
                const int col = n0 + warp_n + ni * 8 + 2 * tg;
                float bi0 = bias[col], bi1 = bias[col + 1];
                float w0 = w2[col],   w1 = w2[col + 1];
                s0 += fmaxf(acc[mi][ni][0] + bi0, 0.f) * w0
                    + fmaxf(acc[mi][ni][1] + bi1, 0.f) * w1;
                s1 += fmaxf(acc[mi][ni][2] + bi0, 0.f) * w0
                    + fmaxf(acc[mi][ni][3] + bi1, 0.f) * w1;
            }
            #pragma unroll
            for (int o = 1; o <= 2; o <<= 1) {
                s0 += __shfl_xor_sync(0xFFFFFFFFu, s0, o);
                s1 += __shfl_xor_sync(0xFFFFFFFFu, s1, o);
            }
            if (tg == 0) {
                const int rr = m0 + warp_m + mi * 16 + g;
                // per (tile,row): exactly 2 adds (warp_n halves) -> deterministic
                atomicAdd(&part[(size_t)blockIdx.x * BDIM + rr],     s0);
                atomicAdd(&part[(size_t)blockIdx.x * BDIM + rr + 8], s1);
            }
        }
    }
    #undef BKP
#endif
}

// ---------------------------------------------------------------------------
// Finalize: sum per-tile partials in fixed order, sigmoid, broadcast x9.
// tiles 0-7 = coop, 8-11 = cov, 12-15 = trk.
// ---------------------------------------------------------------------------
__global__ void k_finalize(const float* __restrict__ part,
                           const float* __restrict__ bc2,
                           const float* __restrict__ bt2,
                           const float* __restrict__ bk2,
                           float* __restrict__ out) {
    int r = blockIdx.x * blockDim.x + threadIdx.x;
    if (r >= BDIM) return;
    float coop = 0.f, cov = 0.f, trk = 0.f;
    #pragma unroll
    for (int t = 0; t < 8; t++)  coop += part[(size_t)t * BDIM + r];
    #pragma unroll
    for (int t = 8; t < 12; t++) cov  += part[(size_t)t * BDIM + r];
    #pragma unroll
    for (int t = 12; t < 16; t++) trk += part[(size_t)t * BDIM + r];
    coop = 1.f / (1.f + expf(-(coop + bk2[0])));
    cov  = 1.f / (1.f + expf(-(cov  + bc2[0])));
    trk  = 1.f / (1.f + expf(-(trk  + bt2[0])));
    float* o0 = out + (size_t)r * NAG;
    float* o1 = out + (size_t)BDIM * NAG + (size_t)r * NAG;
    float* o2 = out + (size_t)2 * BDIM * NAG + (size_t)r * NAG;
    #pragma unroll
    for (int j = 0; j < NAG; j++) { o0[j] = cov; o1[j] = trk; o2[j] = coop; }
}

// ---------------------------------------------------------------------------
// Launch
// ---------------------------------------------------------------------------
extern "C" void kernel_launch(void* const* d_in, const int* in_sizes, int n_in,
                              void* d_out, int out_size) {
    (void)in_sizes; (void)n_in; (void)out_size;

    const float* obs = (const float*)d_in[0];
    const float* W1  = (const float*)d_in[2];
    const float* b1  = (const float*)d_in[3];
    const float* W2  = (const float*)d_in[4];
    const float* b2  = (const float*)d_in[5];
    const float* Wc1 = (const float*)d_in[6];
    const float* bc1 = (const float*)d_in[7];
    const float* Wc2 = (const float*)d_in[8];
    const float* bc2 = (const float*)d_in[9];
    const float* Wt1 = (const float*)d_in[10];
    const float* bt1 = (const float*)d_in[11];
    const float* Wt2 = (const float*)d_in[12];
    const float* bt2 = (const float*)d_in[13];
    const float* Wk1 = (const float*)d_in[14];
    const float* bk1 = (const float*)d_in[15];
    const float* Wk2 = (const float*)d_in[16];
    const float* bk2 = (const float*)d_in[17];
    float* out = (float*)d_out;

    void *p_obs, *p_W1t, *p_W2t, *p_Wall, *p_ball, *p_w2, *p_g1, *p_g2, *p_part;
    cudaGetSymbolAddress(&p_obs,  g_obs);
    cudaGetSymbolAddress(&p_W1t,  g_W1t);
    cudaGetSymbolAddress(&p_W2t,  g_W2t);
    cudaGetSymbolAddress(&p_Wall, g_Wall);
    cudaGetSymbolAddress(&p_ball, g_ball);
    cudaGetSymbolAddress(&p_w2,   g_w2v);
    cudaGetSymbolAddress(&p_g1,   g_g1);
    cudaGetSymbolAddress(&p_g2,   g_g2);
    cudaGetSymbolAddress(&p_part, g_part);

    // Detect which device body got compiled: the fallback has ~73KB static smem,
    // the tcgen05 body has none (dynamic).
    cudaFuncAttributes fa{};
    cudaFuncGetAttributes(&fa, k_gemm<false>);
    const bool tc = (fa.sharedSizeBytes < 8192);
    size_t dyn = 0;
    if (tc) {
        cudaFuncSetAttribute(k_gemm<false>,
                             cudaFuncAttributeMaxDynamicSharedMemorySize, TC_SMEM);
        cudaFuncSetAttribute(k_gemm<true>,
                             cudaFuncAttributeMaxDynamicSharedMemorySize, TC_SMEM);
        dyn = TC_SMEM;
    }

    // prep
    k_cvt_bf16_v4<<<2048, 256>>>((const float4*)obs, (__nv_bfloat16*)p_obs,
                                 BDIM * OBSD / 4);
    k_prep_weights<<<dim3(32, 32, 5), dim3(32, 8)>>>(W1, W2, Wc1, Wt1, Wk1);
    k_head_vecs_zero<<<(NTILES * BDIM + 255) / 256, 256>>>(bk1, Wk2, bc1, Wc2, bt1, Wt2);

    // GEMM1: g1 = relu(obs @ W1 + b1)
    k_gemm<false><<<dim3(HD / 128, BDIM / 128), 256, dyn>>>(
        (const __nv_bfloat16*)p_obs, (const __nv_bfloat16*)p_W1t, b1, nullptr,
        (__nv_bfloat16*)p_g1, nullptr, OBSD, HD);

    // GEMM2: g2 = relu(g1 @ W2 + b2)
    k_gemm<false><<<dim3(HD / 128, BDIM / 128), 256, dyn>>>(
        (const __nv_bfloat16*)p_g1, (const __nv_bfloat16*)p_W2t, b2, nullptr,
        (__nv_bfloat16*)p_g2, nullptr, HD, HD);

    // GEMM3 (fused heads): part[tile][r] += relu(g2 @ Wall + ball)[r,:] . w2
    k_gemm<true><<<dim3(NTILES, BDIM / 128), 256, dyn>>>(
        (const __nv_bfloat16*)p_g2, (const __nv_bfloat16*)p_Wall,
        (const float*)p_ball, (const float*)p_w2,
        nullptr, (float*)p_part, HD, NTOTH);

    // finalize
    k_finalize<<<(BDIM + 255) / 256, 256>>>((const float*)p_part, bc2, bt2, bk2, out);
}